// round 10
// baseline (speedup 1.0000x reference)
#include <cuda_runtime.h>
#include <cuda_bf16.h>

#define T_STEPS 32768
#define IN_SIZE 1024
#define HID     64
#define GATES   256   // 4 * HID
#define T_TILE  32                       // timesteps per GEMM producer tile
#define NTILES  (T_STEPS / T_TILE)       // 1024

// Scratch: precomputed input projection, (T, 4H) row-major. 33.5 MB static.
__device__ float g_xproj[T_STEPS * GATES];
// Producer->consumer readiness flags (one per tile). Zero-initialized at
// module load; reset to 0 by the consumer at the end of EVERY run, so each
// graph replay starts clean (deterministic).
__device__ __align__(16) int g_tile_ready[NTILES];

// ---------------------------------------------------------------------------
// Math helpers
// ---------------------------------------------------------------------------
__device__ __forceinline__ float htanh(float x) {          // MUFU.TANH
    float r;
    asm("tanh.approx.f32 %0, %1;" : "=f"(r) : "f"(x));
    return r;
}
__device__ __forceinline__ void ffma2(unsigned long long& acc,
                                      unsigned long long a,
                                      unsigned long long b) {
    asm("fma.rn.f32x2 %0, %1, %2, %0;" : "+l"(acc) : "l"(a), "l"(b));
}
__device__ __forceinline__ unsigned long long fadd2(unsigned long long a,
                                                    unsigned long long b) {
    unsigned long long r;
    asm("add.rn.f32x2 %0, %1, %2;" : "=l"(r) : "l"(a), "l"(b));
    return r;
}
__device__ __forceinline__ float2 unpack2(unsigned long long v) {
    float2 r;
    asm("mov.b64 {%0, %1}, %2;" : "=f"(r.x), "=f"(r.y) : "l"(v));
    return r;
}

// ---------------------------------------------------------------------------
// Producer: one 32-timestep x 256-gate tile of x_proj.
// ---------------------------------------------------------------------------
__device__ void gemm_tile_body(int tile,
                               const float* __restrict__ spec,
                               const float* __restrict__ W_ih,
                               const float* __restrict__ b_ih,
                               const float* __restrict__ b_hh)
{
    __shared__ float sS[8][T_TILE];  // [kk][t]
    __shared__ float sW[8][GATES];   // [kk][j]

    const int tid = threadIdx.x;
    const int t0  = tile * T_TILE;
    const int tj  = (tid & 31) * 8;   // j base (0..248)
    const int tt  = (tid >> 5) * 4;   // t base within tile (0..28)

    float acc[4][8];
#pragma unroll
    for (int i = 0; i < 4; i++)
#pragma unroll
        for (int j = 0; j < 8; j++) acc[i][j] = 0.f;

    const int krow = tid >> 5;   // 0..7
    const int tcol = tid & 31;   // 0..31

    for (int k0 = 0; k0 < IN_SIZE; k0 += 8) {
        sS[krow][tcol] = spec[(size_t)(k0 + krow) * T_STEPS + t0 + tcol];
        float4 wa = *reinterpret_cast<const float4*>(W_ih + (size_t)tid * IN_SIZE + k0);
        float4 wb = *reinterpret_cast<const float4*>(W_ih + (size_t)tid * IN_SIZE + k0 + 4);
        sW[0][tid] = wa.x; sW[1][tid] = wa.y; sW[2][tid] = wa.z; sW[3][tid] = wa.w;
        sW[4][tid] = wb.x; sW[5][tid] = wb.y; sW[6][tid] = wb.z; sW[7][tid] = wb.w;
        __syncthreads();

#pragma unroll
        for (int kk = 0; kk < 8; kk++) {
            float4 s0 = *reinterpret_cast<const float4*>(&sS[kk][tt]);
            float4 w0 = *reinterpret_cast<const float4*>(&sW[kk][tj]);
            float4 w1 = *reinterpret_cast<const float4*>(&sW[kk][tj + 4]);
            float sv[4] = {s0.x, s0.y, s0.z, s0.w};
            float wv[8] = {w0.x, w0.y, w0.z, w0.w, w1.x, w1.y, w1.z, w1.w};
#pragma unroll
            for (int i = 0; i < 4; i++)
#pragma unroll
                for (int j = 0; j < 8; j++)
                    acc[i][j] = fmaf(sv[i], wv[j], acc[i][j]);
        }
        __syncthreads();
    }

    float bias[8];
#pragma unroll
    for (int j = 0; j < 8; j++) bias[j] = b_ih[tj + j] + b_hh[tj + j];

#pragma unroll
    for (int i = 0; i < 4; i++) {
        const int t = t0 + tt + i;
        float4 o0, o1;
        o0.x = acc[i][0] + bias[0]; o0.y = acc[i][1] + bias[1];
        o0.z = acc[i][2] + bias[2]; o0.w = acc[i][3] + bias[3];
        o1.x = acc[i][4] + bias[4]; o1.y = acc[i][5] + bias[5];
        o1.z = acc[i][6] + bias[6]; o1.w = acc[i][7] + bias[7];
        *reinterpret_cast<float4*>(&g_xproj[(size_t)t * GATES + tj])     = o0;
        *reinterpret_cast<float4*>(&g_xproj[(size_t)t * GATES + tj + 4]) = o1;
    }

    // Publish: every thread fences its own stores, then one thread raises flag
    __threadfence();
    __syncthreads();
    if (tid == 0) atomicExch(&g_tile_ready[tile], 1);
}

// Consumer-side waits (called by tid 0 only); volatile loads bypass L1.
__device__ __forceinline__ void wait_tiles4(int i) {
    const volatile int* f = g_tile_ready;
    for (;;) {
        int a = f[i], b = f[i + 1], c2 = f[i + 2], d = f[i + 3];
        if (a && b && c2 && d) return;
    }
}
__device__ __forceinline__ void wait_tile1(int i) {
    const volatile int* f = g_tile_ready;
    while (!f[i]) {}
}

// ---------------------------------------------------------------------------
// Consumer: sequential LSTM (block 0), 256 threads (8 warps, 2/SMSP).
// Thread = (unit u = tid>>2, gate = tid&3); full 64-weight row in registers
// (32 FFMA2); 4-lane shfl gate exchange; MUFU.TANH; double-buffered h; one
// __syncthreads per step; depth-8 xproj prefetch ring (8x unrolled).
// Waits on producer flags once per 128-step chunk.
// ---------------------------------------------------------------------------
__device__ void lstm_body(const float* __restrict__ W_hh, float* __restrict__ out)
{
    __shared__ __align__(16) float h_sh[2][HID];

    const int tid  = threadIdx.x;
    const int u    = tid >> 2;
    const int gate = tid & 3;         // 0:i 1:f 2:g 3:o
    const int lane = tid & 31;
    const int lbase = lane & ~3;
    const int row  = gate * HID + u;

    unsigned long long wq[HID / 2];
    {
        const ulonglong2* wp =
            reinterpret_cast<const ulonglong2*>(W_hh + (size_t)row * HID);
#pragma unroll
        for (int i = 0; i < HID / 8; i++) {
            ulonglong2 v0 = wp[2 * i];
            ulonglong2 v1 = wp[2 * i + 1];
            wq[4 * i]     = v0.x; wq[4 * i + 1] = v0.y;
            wq[4 * i + 2] = v1.x; wq[4 * i + 3] = v1.y;
        }
    }

    const float am = (gate == 2) ? 1.f : 0.5f;
    const float aq = am;
    const float ar = (gate == 2) ? 0.f : 0.5f;

    float c = 0.f;
    if (tid < HID) h_sh[0][tid] = 0.f;

    // Wait for tiles 0..4 (covers chunk 0 consumption + prefetch spill)
    if (tid == 0) { wait_tiles4(0); wait_tile1(4); }
    __threadfence();
    __syncthreads();

    // Depth-8 prefetch ring warm-up (t = 0..7, tile 0)
    float xf0 = g_xproj[0 * GATES + row];
    float xf1 = g_xproj[1 * GATES + row];
    float xf2 = g_xproj[2 * GATES + row];
    float xf3 = g_xproj[3 * GATES + row];
    float xf4 = g_xproj[4 * GATES + row];
    float xf5 = g_xproj[5 * GATES + row];
    float xf6 = g_xproj[6 * GATES + row];
    float xf7 = g_xproj[7 * GATES + row];
    __syncthreads();

#define LSTM_STEP(XSLOT, RBUF, TNEXT)                                        \
    {                                                                        \
        const float xc = XSLOT;                                              \
        const int tld = ((TNEXT) < T_STEPS) ? (TNEXT) : (T_STEPS - 1);       \
        XSLOT = g_xproj[(size_t)tld * GATES + row];                          \
        unsigned long long a0 = 0ull, a1 = 0ull, a2 = 0ull, a3 = 0ull;       \
        const ulonglong2* hp =                                               \
            reinterpret_cast<const ulonglong2*>(&h_sh[(RBUF)][0]);           \
        _Pragma("unroll")                                                    \
        for (int k = 0; k < HID / 8; k++) {                                  \
            ulonglong2 hA = hp[2 * k];                                       \
            ulonglong2 hB = hp[2 * k + 1];                                   \
            ffma2(a0, hA.x, wq[4 * k]);                                      \
            ffma2(a1, hA.y, wq[4 * k + 1]);                                  \
            ffma2(a2, hB.x, wq[4 * k + 2]);                                  \
            ffma2(a3, hB.y, wq[4 * k + 3]);                                  \
        }                                                                    \
        float2 fs = unpack2(fadd2(fadd2(a0, a1), fadd2(a2, a3)));            \
        const float a = xc + (fs.x + fs.y);                                  \
        const float act = fmaf(aq, htanh(am * a), ar);                       \
        const float i_a = __shfl_sync(0xffffffffu, act, lbase + 0);          \
        const float f_a = __shfl_sync(0xffffffffu, act, lbase + 1);          \
        const float g_a = __shfl_sync(0xffffffffu, act, lbase + 2);          \
        const float o_a = __shfl_sync(0xffffffffu, act, lbase + 3);          \
        c = fmaf(f_a, c, i_a * g_a);                                         \
        const float th = htanh(c);                                           \
        if (gate == 0) h_sh[(RBUF) ^ 1][u] = o_a * th;                       \
        __syncthreads();                                                     \
    }

    // 256 chunks x 128 steps; chunk ch covers tiles 4ch..4ch+3 (+spill 4ch+4)
    for (int ch = 0; ch < T_STEPS / 128; ch++) {
        if (ch > 0) {
            if (tid == 0) {
                wait_tiles4(4 * ch);                       // 4ch..4ch+3
                if (4 * ch + 4 < NTILES) wait_tile1(4 * ch + 4);
            }
            __threadfence();
            __syncthreads();
        }
        const int tb = ch * 128;
#pragma unroll 1
        for (int tt = 0; tt < 128; tt += 8) {
            const int t = tb + tt;
            LSTM_STEP(xf0, 0, t + 8);
            LSTM_STEP(xf1, 1, t + 9);
            LSTM_STEP(xf2, 0, t + 10);
            LSTM_STEP(xf3, 1, t + 11);
            LSTM_STEP(xf4, 0, t + 12);
            LSTM_STEP(xf5, 1, t + 13);
            LSTM_STEP(xf6, 0, t + 14);
            LSTM_STEP(xf7, 1, t + 15);
        }
    }
#undef LSTM_STEP

    // log_softmax over final h (accurate libm; runs once). Final h in buf 0.
    if (tid < HID) {
        const float* hf = h_sh[T_STEPS & 1];
        float m = -1e30f;
#pragma unroll 8
        for (int k = 0; k < HID; k++) m = fmaxf(m, hf[k]);
        float sum = 0.f;
#pragma unroll 8
        for (int k = 0; k < HID; k++) sum += expf(hf[k] - m);
        out[tid] = hf[tid] - m - logf(sum);
    }

    // Reset flags for the next graph replay (all producers already done:
    // every flag was observed == 1 above).
    __syncthreads();
    for (int i = tid; i < NTILES; i += 256) g_tile_ready[i] = 0;
    __threadfence();
}

// ---------------------------------------------------------------------------
// Fused persistent kernel: block 0 = LSTM consumer, blocks 1..NTILES = GEMM
// producers. Producers drain independently of the consumer (no deadlock).
// ---------------------------------------------------------------------------
__global__ void __launch_bounds__(256, 1)
fused_lstm_kernel(const float* __restrict__ spec,
                  const float* __restrict__ W_ih,
                  const float* __restrict__ W_hh,
                  const float* __restrict__ b_ih,
                  const float* __restrict__ b_hh,
                  float* __restrict__ out)
{
    if (blockIdx.x == 0) {
        lstm_body(W_hh, out);
    } else {
        gemm_tile_body(blockIdx.x - 1, spec, W_ih, b_ih, b_hh);
    }
}

// ---------------------------------------------------------------------------
// Launch: inputs in metadata order: spectrogram, W_ih, W_hh, b_ih, b_hh
// ---------------------------------------------------------------------------
extern "C" void kernel_launch(void* const* d_in, const int* in_sizes, int n_in,
                              void* d_out, int out_size)
{
    const float* spec = (const float*)d_in[0];
    const float* W_ih = (const float*)d_in[1];
    const float* W_hh = (const float*)d_in[2];
    const float* b_ih = (const float*)d_in[3];
    const float* b_hh = (const float*)d_in[4];
    float* out = (float*)d_out;

    fused_lstm_kernel<<<NTILES + 1, 256>>>(spec, W_ih, W_hh, b_ih, b_hh, out);
}

// round 11
// speedup vs baseline: 1.0577x; 1.0577x over previous
#include <cuda_runtime.h>
#include <cuda_bf16.h>

#define T_STEPS 32768
#define IN_SIZE 1024
#define HID     64
#define GATES   256   // 4 * HID
#define CHUNK   16    // timesteps staged per cp.async.bulk (16KB)
#define NCHUNK  (T_STEPS / CHUNK)

// Scratch: precomputed input projection, (T, 4H) row-major. 33.5 MB static.
__device__ float g_xproj[T_STEPS * GATES];

// ---------------------------------------------------------------------------
// Kernel 1: x_proj[t][j] = sum_k spec[k][t] * W_ih[j][k] + b_ih[j] + b_hh[j]
// Tiled FP32 GEMM: block = 64 timesteps x 256 gates, BK = 8, 256 threads,
// each thread computes an 8x8 (t x j) micro-tile. (R9 version, unchanged.)
// ---------------------------------------------------------------------------
__global__ void __launch_bounds__(256, 1)
gemm_xproj_kernel(const float* __restrict__ spec,
                  const float* __restrict__ W_ih,
                  const float* __restrict__ b_ih,
                  const float* __restrict__ b_hh)
{
    __shared__ float sS[8][64];    // [kk][t]
    __shared__ float sW[8][GATES]; // [kk][j]

    const int tid = threadIdx.x;
    const int t0  = blockIdx.x * 64;
    const int tj  = (tid & 31) * 8;  // j base (0..248)
    const int tt  = (tid >> 5) * 8;  // t base within tile (0..56)

    float acc[8][8];
#pragma unroll
    for (int i = 0; i < 8; i++)
#pragma unroll
        for (int j = 0; j < 8; j++) acc[i][j] = 0.f;

    const int krow = tid >> 6;   // 0..3
    const int tcol = tid & 63;   // 0..63

    for (int k0 = 0; k0 < IN_SIZE; k0 += 8) {
        sS[krow][tcol]     = spec[(size_t)(k0 + krow) * T_STEPS + t0 + tcol];
        sS[krow + 4][tcol] = spec[(size_t)(k0 + krow + 4) * T_STEPS + t0 + tcol];
        float4 wa = *reinterpret_cast<const float4*>(W_ih + (size_t)tid * IN_SIZE + k0);
        float4 wb = *reinterpret_cast<const float4*>(W_ih + (size_t)tid * IN_SIZE + k0 + 4);
        sW[0][tid] = wa.x; sW[1][tid] = wa.y; sW[2][tid] = wa.z; sW[3][tid] = wa.w;
        sW[4][tid] = wb.x; sW[5][tid] = wb.y; sW[6][tid] = wb.z; sW[7][tid] = wb.w;
        __syncthreads();

#pragma unroll
        for (int kk = 0; kk < 8; kk++) {
            float4 s0 = *reinterpret_cast<const float4*>(&sS[kk][tt]);
            float4 s1 = *reinterpret_cast<const float4*>(&sS[kk][tt + 4]);
            float4 w0 = *reinterpret_cast<const float4*>(&sW[kk][tj]);
            float4 w1 = *reinterpret_cast<const float4*>(&sW[kk][tj + 4]);
            float sv[8] = {s0.x, s0.y, s0.z, s0.w, s1.x, s1.y, s1.z, s1.w};
            float wv[8] = {w0.x, w0.y, w0.z, w0.w, w1.x, w1.y, w1.z, w1.w};
#pragma unroll
            for (int i = 0; i < 8; i++)
#pragma unroll
                for (int j = 0; j < 8; j++)
                    acc[i][j] = fmaf(sv[i], wv[j], acc[i][j]);
        }
        __syncthreads();
    }

    float bias[8];
#pragma unroll
    for (int j = 0; j < 8; j++) bias[j] = b_ih[tj + j] + b_hh[tj + j];

#pragma unroll
    for (int i = 0; i < 8; i++) {
        const int t = t0 + tt + i;
        float4 o0, o1;
        o0.x = acc[i][0] + bias[0]; o0.y = acc[i][1] + bias[1];
        o0.z = acc[i][2] + bias[2]; o0.w = acc[i][3] + bias[3];
        o1.x = acc[i][4] + bias[4]; o1.y = acc[i][5] + bias[5];
        o1.z = acc[i][6] + bias[6]; o1.w = acc[i][7] + bias[7];
        *reinterpret_cast<float4*>(&g_xproj[(size_t)t * GATES + tj])     = o0;
        *reinterpret_cast<float4*>(&g_xproj[(size_t)t * GATES + tj + 4]) = o1;
    }
}

// ---------------------------------------------------------------------------
// Math helpers
// ---------------------------------------------------------------------------
__device__ __forceinline__ float htanh(float x) {          // MUFU.TANH
    float r;
    asm("tanh.approx.f32 %0, %1;" : "=f"(r) : "f"(x));
    return r;
}
__device__ __forceinline__ void ffma2(unsigned long long& acc,
                                      unsigned long long a,
                                      unsigned long long b) {
    asm("fma.rn.f32x2 %0, %1, %2, %0;" : "+l"(acc) : "l"(a), "l"(b));
}
__device__ __forceinline__ unsigned long long fadd2(unsigned long long a,
                                                    unsigned long long b) {
    unsigned long long r;
    asm("add.rn.f32x2 %0, %1, %2;" : "=l"(r) : "l"(a), "l"(b));
    return r;
}
__device__ __forceinline__ float2 unpack2(unsigned long long v) {
    float2 r;
    asm("mov.b64 {%0, %1}, %2;" : "=f"(r.x), "=f"(r.y) : "l"(v));
    return r;
}
__device__ __forceinline__ unsigned smem_u32(const void* p) {
    return (unsigned)__cvta_generic_to_shared(p);
}

// ---------------------------------------------------------------------------
// Kernel 2: sequential LSTM, single block of 256 threads (8 warps, 2/SMSP).
// Thread = (unit u = tid>>2, gate = tid&3); full 64-weight row in registers
// (32 FFMA2); 4-lane shfl gate exchange; MUFU.TANH; double-buffered h; one
// __syncthreads per step.
// R11 change: xproj staged into smem via double-buffered cp.async.bulk
// (16KB / 16 steps, mbarrier expect_tx). Per-step x read = LDS, no LDG.
// ---------------------------------------------------------------------------
__global__ void __launch_bounds__(256, 1)
lstm_seq_kernel(const float* __restrict__ W_hh, float* __restrict__ out)
{
    __shared__ __align__(128) float s_x[2][CHUNK * GATES];   // 2 x 16KB
    __shared__ __align__(16)  float h_sh[2][HID];
    __shared__ __align__(8)   unsigned long long s_mbar[2];

    const int tid  = threadIdx.x;
    const int u    = tid >> 2;        // hidden unit 0..63
    const int gate = tid & 3;         // 0:i 1:f 2:g 3:o
    const int lane = tid & 31;
    const int lbase = lane & ~3;      // first lane of this unit's 4-lane group
    const int row  = gate * HID + u;  // W_hh / x_proj row for this thread

    // Load weight row as 32 packed f32 pairs (64 regs)
    unsigned long long wq[HID / 2];
    {
        const ulonglong2* wp =
            reinterpret_cast<const ulonglong2*>(W_hh + (size_t)row * HID);
#pragma unroll
        for (int i = 0; i < HID / 8; i++) {
            ulonglong2 v0 = wp[2 * i];
            ulonglong2 v1 = wp[2 * i + 1];
            wq[4 * i]     = v0.x; wq[4 * i + 1] = v0.y;
            wq[4 * i + 2] = v1.x; wq[4 * i + 3] = v1.y;
        }
    }

    // Activation folding: act = q * tanh(m * a) + r
    const float am = (gate == 2) ? 1.f : 0.5f;
    const float aq = am;
    const float ar = (gate == 2) ? 0.f : 0.5f;

    const unsigned mb0 = smem_u32(&s_mbar[0]);
    const unsigned mb1 = smem_u32(&s_mbar[1]);
    const unsigned bufaddr0 = smem_u32(&s_x[0][0]);
    const unsigned bufaddr1 = smem_u32(&s_x[1][0]);
    const unsigned CPBYTES = CHUNK * GATES * 4;   // 16384

    float c = 0.f;
    if (tid < HID) h_sh[0][tid] = 0.f;

    // Init mbarriers + issue the first two chunk loads (thread 0)
    if (tid == 0) {
        asm volatile("mbarrier.init.shared.b64 [%0], 1;" :: "r"(mb0) : "memory");
        asm volatile("mbarrier.init.shared.b64 [%0], 1;" :: "r"(mb1) : "memory");
        asm volatile("fence.proxy.async.shared::cta;" ::: "memory");
        // chunk 0 -> buf 0
        asm volatile("mbarrier.arrive.expect_tx.shared.b64 _, [%0], %1;"
                     :: "r"(mb0), "r"(CPBYTES) : "memory");
        asm volatile("cp.async.bulk.shared::cta.global.mbarrier::complete_tx::bytes"
                     " [%0], [%1], %2, [%3];"
                     :: "r"(bufaddr0), "l"((const void*)&g_xproj[0]),
                        "r"(CPBYTES), "r"(mb0) : "memory");
        // chunk 1 -> buf 1
        asm volatile("mbarrier.arrive.expect_tx.shared.b64 _, [%0], %1;"
                     :: "r"(mb1), "r"(CPBYTES) : "memory");
        asm volatile("cp.async.bulk.shared::cta.global.mbarrier::complete_tx::bytes"
                     " [%0], [%1], %2, [%3];"
                     :: "r"(bufaddr1), "l"((const void*)&g_xproj[CHUNK * GATES]),
                        "r"(CPBYTES), "r"(mb1) : "memory");
    }
    __syncthreads();

#define LSTM_STEP(XBASE, TT, RBUF)                                           \
    {                                                                        \
        const float xc = (XBASE)[(TT) * GATES + row];                        \
        unsigned long long a0 = 0ull, a1 = 0ull, a2 = 0ull, a3 = 0ull;       \
        const ulonglong2* hp =                                               \
            reinterpret_cast<const ulonglong2*>(&h_sh[(RBUF)][0]);           \
        _Pragma("unroll")                                                    \
        for (int k = 0; k < HID / 8; k++) {                                  \
            ulonglong2 hA = hp[2 * k];                                       \
            ulonglong2 hB = hp[2 * k + 1];                                   \
            ffma2(a0, hA.x, wq[4 * k]);                                      \
            ffma2(a1, hA.y, wq[4 * k + 1]);                                  \
            ffma2(a2, hB.x, wq[4 * k + 2]);                                  \
            ffma2(a3, hB.y, wq[4 * k + 3]);                                  \
        }                                                                    \
        float2 fs = unpack2(fadd2(fadd2(a0, a1), fadd2(a2, a3)));            \
        const float a = xc + (fs.x + fs.y);                                  \
        const float act = fmaf(aq, htanh(am * a), ar);                       \
        const float i_a = __shfl_sync(0xffffffffu, act, lbase + 0);          \
        const float f_a = __shfl_sync(0xffffffffu, act, lbase + 1);          \
        const float g_a = __shfl_sync(0xffffffffu, act, lbase + 2);          \
        const float o_a = __shfl_sync(0xffffffffu, act, lbase + 3);          \
        c = fmaf(f_a, c, i_a * g_a);                                         \
        const float th = htanh(c);                                           \
        if (gate == 0) h_sh[(RBUF) ^ 1][u] = o_a * th;                       \
        __syncthreads();                                                     \
    }

    for (int ch = 0; ch < NCHUNK; ch++) {
        const int b = ch & 1;
        const unsigned mb = b ? mb1 : mb0;
        const unsigned ph = (unsigned)((ch >> 1) & 1);
        const float* xb = &s_x[b][0];

        // Wait for this chunk's data (fast-path try_wait when complete)
        {
            unsigned done;
            asm volatile(
                "{\n\t.reg .pred p;\n\t"
                "mbarrier.try_wait.parity.acquire.cta.shared::cta.b64 p, [%1], %2;\n\t"
                "selp.b32 %0, 1, 0, p;\n\t}"
                : "=r"(done) : "r"(mb), "r"(ph) : "memory");
            while (!done) {
                asm volatile(
                    "{\n\t.reg .pred p;\n\t"
                    "mbarrier.try_wait.parity.acquire.cta.shared::cta.b64 p, [%1], %2, 0x989680;\n\t"
                    "selp.b32 %0, 1, 0, p;\n\t}"
                    : "=r"(done) : "r"(mb), "r"(ph) : "memory");
            }
        }

        // 16 steps; each step ends with __syncthreads (so after the last one,
        // all threads are done reading this buffer)
        LSTM_STEP(xb, 0,  0);  LSTM_STEP(xb, 1,  1);
        LSTM_STEP(xb, 2,  0);  LSTM_STEP(xb, 3,  1);
        LSTM_STEP(xb, 4,  0);  LSTM_STEP(xb, 5,  1);
        LSTM_STEP(xb, 6,  0);  LSTM_STEP(xb, 7,  1);
        LSTM_STEP(xb, 8,  0);  LSTM_STEP(xb, 9,  1);
        LSTM_STEP(xb, 10, 0);  LSTM_STEP(xb, 11, 1);
        LSTM_STEP(xb, 12, 0);  LSTM_STEP(xb, 13, 1);
        LSTM_STEP(xb, 14, 0);  LSTM_STEP(xb, 15, 1);

        // Refill this buffer with chunk ch+2 (safe: all reads completed)
        if (tid == 0 && ch + 2 < NCHUNK) {
            const unsigned dst = b ? bufaddr1 : bufaddr0;
            asm volatile("mbarrier.arrive.expect_tx.shared.b64 _, [%0], %1;"
                         :: "r"(mb), "r"(CPBYTES) : "memory");
            asm volatile("cp.async.bulk.shared::cta.global.mbarrier::complete_tx::bytes"
                         " [%0], [%1], %2, [%3];"
                         :: "r"(dst),
                            "l"((const void*)&g_xproj[(size_t)(ch + 2) * CHUNK * GATES]),
                            "r"(CPBYTES), "r"(mb) : "memory");
        }
    }
#undef LSTM_STEP

    // log_softmax over final h (accurate libm; runs once). Final h in buf 0.
    if (tid < HID) {
        const float* hf = h_sh[T_STEPS & 1];
        float m = -1e30f;
#pragma unroll 8
        for (int k = 0; k < HID; k++) m = fmaxf(m, hf[k]);
        float sum = 0.f;
#pragma unroll 8
        for (int k = 0; k < HID; k++) sum += expf(hf[k] - m);
        out[tid] = hf[tid] - m - logf(sum);
    }
}

// ---------------------------------------------------------------------------
// Launch: inputs in metadata order: spectrogram, W_ih, W_hh, b_ih, b_hh
// ---------------------------------------------------------------------------
extern "C" void kernel_launch(void* const* d_in, const int* in_sizes, int n_in,
                              void* d_out, int out_size)
{
    const float* spec = (const float*)d_in[0];
    const float* W_ih = (const float*)d_in[1];
    const float* W_hh = (const float*)d_in[2];
    const float* b_ih = (const float*)d_in[3];
    const float* b_hh = (const float*)d_in[4];
    float* out = (float*)d_out;

    gemm_xproj_kernel<<<T_STEPS / 64, 256>>>(spec, W_ih, b_ih, b_hh);
    lstm_seq_kernel<<<1, 256>>>(W_hh, out);
}